// round 9
// baseline (speedup 1.0000x reference)
#include <cuda_runtime.h>
#include <cuda_bf16.h>
#include <cuda_fp16.h>

#define Nn 100000
#define Ee 1600000
#define Dd 128
#define Hh 256
#define Ll 40
#define NB 98   // ceil(Nn / 1024)

// ---------------- scratch ------------------------------------------------------
__device__ int   g_degi[Nn];
__device__ int   g_offs[Nn + 1];
__device__ int   g_col[Ee];
__device__ int   g_part[NB];
__device__ int   g_base[NB];
__device__ float g_dinv[Nn];
__device__ float g_bufA[(size_t)Nn * Dd];     // gather output (fp32)
__device__ float g_bufB[(size_t)Nn * Dd];     // h3 (fp32)
__device__ float g_hid[(size_t)Nn * Hh];      // MLP hidden
__device__ __half g_xh[(size_t)Nn * Dd];      // fp16 x
__device__ __half g_actH[(size_t)Nn * Dd];    // fp16 h1 / h2
// transposed bf16 hi/lo weights [N][K]:
//   W0,W1,W2: 128x128 ; Wm1: 256x128 ; Wm2: 64(pad from 40)x256
#define WT0 0
#define WT1 16384
#define WT2 32768
#define WTM1 49152
#define WTM2 81920
__device__ __nv_bfloat16 g_wtH[98304];
__device__ __nv_bfloat16 g_wtL[98304];

// ---------------- CSR build ----------------------------------------------------
__global__ void k_zero(int* __restrict__ a, int n) {
    int i = blockIdx.x * blockDim.x + threadIdx.x;
    if (i < n) a[i] = 0;
}

__global__ void k_bzero(__nv_bfloat16* __restrict__ a, __nv_bfloat16* __restrict__ b, int n) {
    int i = blockIdx.x * blockDim.x + threadIdx.x;
    if (i < n) { a[i] = __float2bfloat16(0.f); b[i] = __float2bfloat16(0.f); }
}

__global__ void k_count(const int* __restrict__ ei, int* __restrict__ degi, int e) {
    int i = blockIdx.x * blockDim.x + threadIdx.x;
    if (i < e) atomicAdd(&degi[ei[i]], 1);
}

__global__ void k_dinv(const int* __restrict__ degi, float* __restrict__ dinv, int n) {
    int i = blockIdx.x * blockDim.x + threadIdx.x;
    if (i < n) dinv[i] = rsqrtf((float)degi[i] + 1.0f);
}

__global__ void k_scanA(const int* __restrict__ degi, int* __restrict__ part) {
    __shared__ int s[1024];
    int i = blockIdx.x * 1024 + threadIdx.x;
    s[threadIdx.x] = (i < Nn) ? degi[i] : 0;
    __syncthreads();
    for (int d = 512; d > 0; d >>= 1) {
        if (threadIdx.x < d) s[threadIdx.x] += s[threadIdx.x + d];
        __syncthreads();
    }
    if (threadIdx.x == 0) part[blockIdx.x] = s[0];
}

__global__ void k_scanB(const int* __restrict__ part, int* __restrict__ base) {
    __shared__ int s[128];
    int t = threadIdx.x;
    int v = (t < NB) ? part[t] : 0;
    s[t] = v;
    __syncthreads();
    for (int d = 1; d < 128; d <<= 1) {
        int u = (t >= d) ? s[t - d] : 0;
        __syncthreads();
        s[t] += u;
        __syncthreads();
    }
    if (t < NB) base[t] = s[t] - v;
}

__global__ void k_scanC(const int* __restrict__ degi, const int* __restrict__ base,
                        int* __restrict__ offs) {
    __shared__ int s[1024];
    int t = threadIdx.x;
    int i = blockIdx.x * 1024 + t;
    int v = (i < Nn) ? degi[i] : 0;
    s[t] = v;
    __syncthreads();
    for (int d = 1; d < 1024; d <<= 1) {
        int u = (t >= d) ? s[t - d] : 0;
        __syncthreads();
        s[t] += u;
        __syncthreads();
    }
    int exc = s[t] - v + base[blockIdx.x];
    if (i < Nn) {
        offs[i] = exc;
        if (i == Nn - 1) offs[Nn] = exc + v;
    }
}

__global__ void k_fill(const int* __restrict__ ei, const int* __restrict__ offs,
                       int* __restrict__ degi, int* __restrict__ col, int e) {
    int i = blockIdx.x * blockDim.x + threadIdx.x;
    if (i < e) {
        int r = ei[i];
        int c = ei[e + i];
        int pos = offs[r] + atomicSub(&degi[r], 1) - 1;
        col[pos] = c;
    }
}

// ---------------- weight conversion: W[K][N] -> Wt hi/lo [N][K] ---------------
__global__ void k_wconv(const float* __restrict__ W, __nv_bfloat16* __restrict__ H,
                        __nv_bfloat16* __restrict__ L, int K, int N) {
    int i = blockIdx.x * blockDim.x + threadIdx.x;
    if (i < K * N) {
        int k = i / N, n = i % N;
        float w = W[i];
        __nv_bfloat16 h = __float2bfloat16(w);
        __nv_bfloat16 l = __float2bfloat16(w - __bfloat162float(h));
        H[(size_t)n * K + k] = h;
        L[(size_t)n * K + k] = l;
    }
}

// ---------------- fp32 -> fp16 conversion (x once per launch) -----------------
__global__ void k_f2h(const float4* __restrict__ x, uint2* __restrict__ xh, int n4) {
    int t = blockIdx.x * blockDim.x + threadIdx.x;
    if (t < n4) {
        float4 v = x[t];
        __half2 a = __floats2half2_rn(v.x, v.y);
        __half2 b = __floats2half2_rn(v.z, v.w);
        uint2 u;
        u.x = *(unsigned*)&a;
        u.y = *(unsigned*)&b;
        xh[t] = u;
    }
}

// ---------------- aggregation: warp/node, fp16 src, 2-way pipelined -----------
// dst[r] = dinv[r] * ( dinv[r]*src[r] + sum_{c in N(r)} dinv[c]*src[c] )
__device__ __forceinline__ float4 h4_to_f4(uint2 u) {
    float2 f0 = __half22float2(*reinterpret_cast<__half2*>(&u.x));
    float2 f1 = __half22float2(*reinterpret_cast<__half2*>(&u.y));
    return make_float4(f0.x, f0.y, f1.x, f1.y);
}

__global__ void k_gather_h(const int* __restrict__ offs, const int* __restrict__ col,
                           const float* __restrict__ dinv, const uint2* __restrict__ src,
                           float4* __restrict__ dst) {
    int w    = (int)((blockIdx.x * (size_t)blockDim.x + threadIdx.x) >> 5);
    int lane = threadIdx.x & 31;
    if (w >= Nn) return;

    float di = __ldg(&dinv[w]);
    float4 aA = h4_to_f4(__ldg(&src[(size_t)w * 32 + lane]));   // self
    aA.x *= di; aA.y *= di; aA.z *= di; aA.w *= di;
    float4 aB = make_float4(0.f, 0.f, 0.f, 0.f);

    int beg = __ldg(&offs[w]), end = __ldg(&offs[w + 1]);
    int j = beg;
    // 2 edges per iteration: both loads issued before either accumulate,
    // two independent accumulator chains (MLP ~2 without R6's register cost)
    for (; j + 2 <= end; j += 2) {
        int c0 = __ldg(&col[j]);
        int c1 = __ldg(&col[j + 1]);
        float w0 = __ldg(&dinv[c0]);
        float w1 = __ldg(&dinv[c1]);
        uint2 u0 = __ldg(&src[(size_t)c0 * 32 + lane]);
        uint2 u1 = __ldg(&src[(size_t)c1 * 32 + lane]);
        float4 v0 = h4_to_f4(u0);
        float4 v1 = h4_to_f4(u1);
        aA.x = fmaf(w0, v0.x, aA.x); aA.y = fmaf(w0, v0.y, aA.y);
        aA.z = fmaf(w0, v0.z, aA.z); aA.w = fmaf(w0, v0.w, aA.w);
        aB.x = fmaf(w1, v1.x, aB.x); aB.y = fmaf(w1, v1.y, aB.y);
        aB.z = fmaf(w1, v1.z, aB.z); aB.w = fmaf(w1, v1.w, aB.w);
    }
    if (j < end) {
        int c = __ldg(&col[j]);
        float wc = __ldg(&dinv[c]);
        float4 v = h4_to_f4(__ldg(&src[(size_t)c * 32 + lane]));
        aA.x = fmaf(wc, v.x, aA.x); aA.y = fmaf(wc, v.y, aA.y);
        aA.z = fmaf(wc, v.z, aA.z); aA.w = fmaf(wc, v.w, aA.w);
    }
    float4 o;
    o.x = di * (aA.x + aB.x);
    o.y = di * (aA.y + aB.y);
    o.z = di * (aA.z + aB.z);
    o.w = di * (aA.w + aB.w);
    dst[(size_t)w * 32 + lane] = o;
}

// ---------------- bf16 split-precision tensor-core GEMM (R5 proven) -----------
__device__ __forceinline__ void mma16816(float* c, const unsigned* a, unsigned b0, unsigned b1) {
    asm volatile(
        "mma.sync.aligned.m16n8k16.row.col.f32.bf16.bf16.f32 "
        "{%0,%1,%2,%3},{%4,%5,%6,%7},{%8,%9},{%0,%1,%2,%3};"
        : "+f"(c[0]), "+f"(c[1]), "+f"(c[2]), "+f"(c[3])
        : "r"(a[0]), "r"(a[1]), "r"(a[2]), "r"(a[3]), "r"(b0), "r"(b1));
}

// OUTH: write fp16 output (for activations feeding the next gather)
template<int KEL, int NTILE, int NVALID, bool RELU, bool OUTH>
__global__ void k_gemm_tc(const float* __restrict__ A, const __nv_bfloat16* __restrict__ WtH,
                          const __nv_bfloat16* __restrict__ WtL, const float* __restrict__ bias,
                          void* __restrict__ outv, int nrows, int ldc) {
    constexpr int KSTR  = KEL + 8;
    constexpr int NT    = NTILE / 2;   // warp n-extent
    constexpr int NFRAG = NT / 8;
    extern __shared__ __nv_bfloat16 smb[];
    __nv_bfloat16* AsH = smb;
    __nv_bfloat16* AsL = AsH + 128 * KSTR;
    __nv_bfloat16* WsH = AsL + 128 * KSTR;
    __nv_bfloat16* WsL = WsH + NTILE * KSTR;

    int tid = threadIdx.x;
    int m0 = blockIdx.x * 128;
    int n0 = blockIdx.y * NTILE;

    // stage A: fp32 -> bf16 hi/lo
    constexpr int C4 = KEL / 4;
#pragma unroll
    for (int it = 0; it < 128 * C4 / 256; it++) {
        int i = tid + 256 * it;
        int r = i / C4, c4 = i % C4;
        float4 v = (m0 + r < nrows) ? ((const float4*)A)[(size_t)(m0 + r) * C4 + c4]
                                    : make_float4(0.f, 0.f, 0.f, 0.f);
        __nv_bfloat16 h0 = __float2bfloat16(v.x), h1 = __float2bfloat16(v.y);
        __nv_bfloat16 h2 = __float2bfloat16(v.z), h3 = __float2bfloat16(v.w);
        __nv_bfloat16 l0 = __float2bfloat16(v.x - __bfloat162float(h0));
        __nv_bfloat16 l1 = __float2bfloat16(v.y - __bfloat162float(h1));
        __nv_bfloat16 l2 = __float2bfloat16(v.z - __bfloat162float(h2));
        __nv_bfloat16 l3 = __float2bfloat16(v.w - __bfloat162float(h3));
        int o = r * KSTR + c4 * 4;
        *(__nv_bfloat162*)&AsH[o]     = __nv_bfloat162{h0, h1};
        *(__nv_bfloat162*)&AsH[o + 2] = __nv_bfloat162{h2, h3};
        *(__nv_bfloat162*)&AsL[o]     = __nv_bfloat162{l0, l1};
        *(__nv_bfloat162*)&AsL[o + 2] = __nv_bfloat162{l2, l3};
    }
    // stage Wt slice (rows n0..n0+NTILE-1), 16B chunks
    constexpr int C8 = KEL / 8;
    {
        const uint4* GH = (const uint4*)(WtH + (size_t)n0 * KEL);
        const uint4* GL = (const uint4*)(WtL + (size_t)n0 * KEL);
#pragma unroll
        for (int it = 0; it < NTILE * C8 / 256; it++) {
            int i = tid + 256 * it;
            int r = i / C8, c = i % C8;
            *(uint4*)((char*)WsH + r * (KSTR * 2) + c * 16) = GH[r * C8 + c];
            *(uint4*)((char*)WsL + r * (KSTR * 2) + c * 16) = GL[r * C8 + c];
        }
    }
    __syncthreads();

    int lane = tid & 31, wid = tid >> 5;
    int wm = (wid & 3) * 32;
    int wn = (wid >> 2) * NT;
    int g = lane >> 2, t = lane & 3;

    float acc[2][NFRAG][4];
#pragma unroll
    for (int mt = 0; mt < 2; mt++)
#pragma unroll
        for (int nt = 0; nt < NFRAG; nt++)
#pragma unroll
            for (int q = 0; q < 4; q++) acc[mt][nt][q] = 0.f;

#pragma unroll
    for (int ks = 0; ks < KEL / 16; ks++) {
        int k0 = ks * 16;
        unsigned aH[2][4], aL[2][4];
#pragma unroll
        for (int mt = 0; mt < 2; mt++) {
            int r = wm + mt * 16;
            aH[mt][0] = *(const unsigned*)&AsH[(r + g) * KSTR + k0 + 2 * t];
            aH[mt][1] = *(const unsigned*)&AsH[(r + g + 8) * KSTR + k0 + 2 * t];
            aH[mt][2] = *(const unsigned*)&AsH[(r + g) * KSTR + k0 + 8 + 2 * t];
            aH[mt][3] = *(const unsigned*)&AsH[(r + g + 8) * KSTR + k0 + 8 + 2 * t];
            aL[mt][0] = *(const unsigned*)&AsL[(r + g) * KSTR + k0 + 2 * t];
            aL[mt][1] = *(const unsigned*)&AsL[(r + g + 8) * KSTR + k0 + 2 * t];
            aL[mt][2] = *(const unsigned*)&AsL[(r + g) * KSTR + k0 + 8 + 2 * t];
            aL[mt][3] = *(const unsigned*)&AsL[(r + g + 8) * KSTR + k0 + 8 + 2 * t];
        }
#pragma unroll
        for (int nt = 0; nt < NFRAG; nt++) {
            int nn = wn + nt * 8 + g;
            unsigned bH0 = *(const unsigned*)&WsH[nn * KSTR + k0 + 2 * t];
            unsigned bH1 = *(const unsigned*)&WsH[nn * KSTR + k0 + 8 + 2 * t];
            unsigned bL0 = *(const unsigned*)&WsL[nn * KSTR + k0 + 2 * t];
            unsigned bL1 = *(const unsigned*)&WsL[nn * KSTR + k0 + 8 + 2 * t];
#pragma unroll
            for (int mt = 0; mt < 2; mt++) {
                mma16816(acc[mt][nt], aH[mt], bH0, bH1);
                mma16816(acc[mt][nt], aH[mt], bL0, bL1);
                mma16816(acc[mt][nt], aL[mt], bH0, bH1);
            }
        }
    }

    // epilogue
#pragma unroll
    for (int nt = 0; nt < NFRAG; nt++) {
        int cg = n0 + wn + nt * 8 + 2 * t;
        bool cok = cg < NVALID;        // NVALID even, cg even -> covers cg+1
        float bv0 = cok ? bias[cg] : 0.f;
        float bv1 = cok ? bias[cg + 1] : 0.f;
#pragma unroll
        for (int mt = 0; mt < 2; mt++) {
            int r0 = m0 + wm + mt * 16 + g;
            float v0 = acc[mt][nt][0] + bv0, v1 = acc[mt][nt][1] + bv1;
            float v2 = acc[mt][nt][2] + bv0, v3 = acc[mt][nt][3] + bv1;
            if (RELU) {
                v0 = fmaxf(v0, 0.f); v1 = fmaxf(v1, 0.f);
                v2 = fmaxf(v2, 0.f); v3 = fmaxf(v3, 0.f);
            }
            if (OUTH) {
                __half* oh = (__half*)outv;
                if (cok && r0 < nrows)
                    *(__half2*)&oh[(size_t)r0 * ldc + cg] = __floats2half2_rn(v0, v1);
                if (cok && r0 + 8 < nrows)
                    *(__half2*)&oh[(size_t)(r0 + 8) * ldc + cg] = __floats2half2_rn(v2, v3);
            } else {
                float* of = (float*)outv;
                if (cok && r0 < nrows) {
                    of[(size_t)r0 * ldc + cg]     = v0;
                    of[(size_t)r0 * ldc + cg + 1] = v1;
                }
                if (cok && r0 + 8 < nrows) {
                    of[(size_t)(r0 + 8) * ldc + cg]     = v2;
                    of[(size_t)(r0 + 8) * ldc + cg + 1] = v3;
                }
            }
        }
    }
}

#define SMEM_TC  (4 * 128 * 136 * 2)               // 139264 (KEL=128, NTILE=128)
#define SMEM_M2  ((2 * 128 + 2 * 64) * 264 * 2)    // 202752 (KEL=256, NTILE=64)

extern "C" void kernel_launch(void* const* d_in, const int* in_sizes, int n_in,
                              void* d_out, int out_size) {
    const float* x   = (const float*)d_in[0];
    const int*   ei  = (const int*)  d_in[1];
    const float* W0  = (const float*)d_in[2];
    const float* b0  = (const float*)d_in[3];
    const float* W1  = (const float*)d_in[4];
    const float* b1  = (const float*)d_in[5];
    const float* W2  = (const float*)d_in[6];
    const float* b2  = (const float*)d_in[7];
    const float* Wm1 = (const float*)d_in[8];
    const float* bm1 = (const float*)d_in[9];
    const float* Wm2 = (const float*)d_in[10];
    const float* bm2 = (const float*)d_in[11];
    float* out = (float*)d_out;

    const int n = Nn, e = Ee;

    int *degi, *offs, *col, *part, *base;
    float *dinv, *bufA, *bufB, *hid;
    __half *xh, *actH;
    __nv_bfloat16 *wtH, *wtL;
    cudaGetSymbolAddress((void**)&degi, g_degi);
    cudaGetSymbolAddress((void**)&offs, g_offs);
    cudaGetSymbolAddress((void**)&col,  g_col);
    cudaGetSymbolAddress((void**)&part, g_part);
    cudaGetSymbolAddress((void**)&base, g_base);
    cudaGetSymbolAddress((void**)&dinv, g_dinv);
    cudaGetSymbolAddress((void**)&bufA, g_bufA);
    cudaGetSymbolAddress((void**)&bufB, g_bufB);
    cudaGetSymbolAddress((void**)&hid,  g_hid);
    cudaGetSymbolAddress((void**)&xh,   g_xh);
    cudaGetSymbolAddress((void**)&actH, g_actH);
    cudaGetSymbolAddress((void**)&wtH,  g_wtH);
    cudaGetSymbolAddress((void**)&wtL,  g_wtL);

    cudaFuncSetAttribute(k_gemm_tc<128, 128, 128, true, true>,
                         cudaFuncAttributeMaxDynamicSharedMemorySize, SMEM_TC);
    cudaFuncSetAttribute(k_gemm_tc<128, 128, 128, true, false>,
                         cudaFuncAttributeMaxDynamicSharedMemorySize, SMEM_TC);
    cudaFuncSetAttribute(k_gemm_tc<128, 128, 256, true, false>,
                         cudaFuncAttributeMaxDynamicSharedMemorySize, SMEM_TC);
    cudaFuncSetAttribute(k_gemm_tc<256, 64, 40, false, false>,
                         cudaFuncAttributeMaxDynamicSharedMemorySize, SMEM_M2);

    const int TB = 256;
    dim3 gN((n + TB - 1) / TB);
    dim3 gE((e + TB - 1) / TB);
    dim3 gNW(((size_t)n * 32 + TB - 1) / TB);
    dim3 gF2H(((size_t)n * 32 + TB - 1) / TB);
    dim3 gTC((n + 127) / 128, 1);
    dim3 gTC2((n + 127) / 128, 2);

    // ---- CSR build + normalization ----
    k_zero <<<gN, TB>>>(degi, n);
    k_count<<<gE, TB>>>(ei, degi, e);
    k_dinv <<<gN, TB>>>(degi, dinv, n);
    k_scanA<<<NB, 1024>>>(degi, part);
    k_scanB<<<1, 128>>>(part, base);
    k_scanC<<<NB, 1024>>>(degi, base, offs);
    k_fill <<<gE, TB>>>(ei, offs, degi, col, e);

    // ---- weight conversion (transposed bf16 hi/lo; Wm2 zero-padded to 64) ----
    k_bzero<<<(16384 + 255) / 256, 256>>>(wtH + WTM2, wtL + WTM2, 16384);
    k_wconv<<<(128 * 128 + 255) / 256, 256>>>(W0,  wtH + WT0,  wtL + WT0,  128, 128);
    k_wconv<<<(128 * 128 + 255) / 256, 256>>>(W1,  wtH + WT1,  wtL + WT1,  128, 128);
    k_wconv<<<(128 * 128 + 255) / 256, 256>>>(W2,  wtH + WT2,  wtL + WT2,  128, 128);
    k_wconv<<<(128 * 256 + 255) / 256, 256>>>(Wm1, wtH + WTM1, wtL + WTM1, 128, 256);
    k_wconv<<<(256 * 40 + 255) / 256, 256>>>(Wm2, wtH + WTM2, wtL + WTM2, 256, 40);

    // ---- x -> fp16 ----
    k_f2h<<<gF2H, TB>>>((const float4*)x, (uint2*)xh, n * 32);

    // ---- layer 0: gather fp16 x, GEMM -> fp16 h1 ----
    k_gather_h<<<gNW, TB>>>(offs, col, dinv, (const uint2*)xh, (float4*)bufA);
    k_gemm_tc<128, 128, 128, true, true><<<gTC, TB, SMEM_TC>>>(
        bufA, wtH + WT0, wtL + WT0, b0, actH, n, 128);

    // ---- layer 1: gather fp16 h1, GEMM -> fp16 h2 ----
    k_gather_h<<<gNW, TB>>>(offs, col, dinv, (const uint2*)actH, (float4*)bufA);
    k_gemm_tc<128, 128, 128, true, true><<<gTC, TB, SMEM_TC>>>(
        bufA, wtH + WT1, wtL + WT1, b1, actH, n, 128);

    // ---- layer 2: gather fp16 h2, GEMM -> fp32 h3 ----
    k_gather_h<<<gNW, TB>>>(offs, col, dinv, (const uint2*)actH, (float4*)bufA);
    k_gemm_tc<128, 128, 128, true, false><<<gTC, TB, SMEM_TC>>>(
        bufA, wtH + WT2, wtL + WT2, b2, bufB, n, 128);

    // ---- MLP ----
    k_gemm_tc<128, 128, 256, true, false><<<gTC2, TB, SMEM_TC>>>(
        bufB, wtH + WTM1, wtL + WTM1, bm1, hid, n, 256);
    k_gemm_tc<256, 64, 40, false, false><<<gTC, TB, SMEM_M2>>>(
        hid, wtH + WTM2, wtL + WTM2, bm2, out, n, 40);
}

// round 10
// speedup vs baseline: 1.1609x; 1.1609x over previous
#include <cuda_runtime.h>
#include <cuda_bf16.h>
#include <cuda_fp16.h>

#define Nn 100000
#define Ee 1600000
#define Dd 128
#define Hh 256
#define Ll 40
#define NB 98   // ceil(Nn / 1024)

// ---------------- scratch ------------------------------------------------------
__device__ int   g_degi[Nn];
__device__ int   g_offs[Nn + 1];
__device__ int   g_col[Ee];
__device__ int   g_part[NB];
__device__ int   g_base[NB];
__device__ float g_dinv[Nn];
__device__ float g_bufA[(size_t)Nn * Dd];     // gather output (fp32)
__device__ float g_bufB[(size_t)Nn * Dd];     // h3 (fp32)
__device__ float g_hid[(size_t)Nn * Hh];      // MLP hidden
__device__ __half g_xh[(size_t)Nn * Dd];      // fp16 x
__device__ __half g_actH[(size_t)Nn * Dd];    // fp16 h1 / h2
// transposed fp16 hi/lo weights [N][K]:
//   W0,W1,W2: 128x128 ; Wm1: 256x128 ; Wm2: 64(pad from 40)x256
#define WT0 0
#define WT1 16384
#define WT2 32768
#define WTM1 49152
#define WTM2 81920
__device__ __half g_wtH[98304];
__device__ __half g_wtL[98304];

// ---------------- CSR build ----------------------------------------------------
__global__ void k_zero(int* __restrict__ a, int n) {
    int i = blockIdx.x * blockDim.x + threadIdx.x;
    if (i < n) a[i] = 0;
}

__global__ void k_bzero(__half* __restrict__ a, __half* __restrict__ b, int n) {
    int i = blockIdx.x * blockDim.x + threadIdx.x;
    if (i < n) { a[i] = __float2half(0.f); b[i] = __float2half(0.f); }
}

__global__ void k_count(const int* __restrict__ ei, int* __restrict__ degi, int e) {
    int i = blockIdx.x * blockDim.x + threadIdx.x;
    if (i < e) atomicAdd(&degi[ei[i]], 1);
}

__global__ void k_dinv(const int* __restrict__ degi, float* __restrict__ dinv, int n) {
    int i = blockIdx.x * blockDim.x + threadIdx.x;
    if (i < n) dinv[i] = rsqrtf((float)degi[i] + 1.0f);
}

__global__ void k_scanA(const int* __restrict__ degi, int* __restrict__ part) {
    __shared__ int s[1024];
    int i = blockIdx.x * 1024 + threadIdx.x;
    s[threadIdx.x] = (i < Nn) ? degi[i] : 0;
    __syncthreads();
    for (int d = 512; d > 0; d >>= 1) {
        if (threadIdx.x < d) s[threadIdx.x] += s[threadIdx.x + d];
        __syncthreads();
    }
    if (threadIdx.x == 0) part[blockIdx.x] = s[0];
}

__global__ void k_scanB(const int* __restrict__ part, int* __restrict__ base) {
    __shared__ int s[128];
    int t = threadIdx.x;
    int v = (t < NB) ? part[t] : 0;
    s[t] = v;
    __syncthreads();
    for (int d = 1; d < 128; d <<= 1) {
        int u = (t >= d) ? s[t - d] : 0;
        __syncthreads();
        s[t] += u;
        __syncthreads();
    }
    if (t < NB) base[t] = s[t] - v;
}

__global__ void k_scanC(const int* __restrict__ degi, const int* __restrict__ base,
                        int* __restrict__ offs) {
    __shared__ int s[1024];
    int t = threadIdx.x;
    int i = blockIdx.x * 1024 + t;
    int v = (i < Nn) ? degi[i] : 0;
    s[t] = v;
    __syncthreads();
    for (int d = 1; d < 1024; d <<= 1) {
        int u = (t >= d) ? s[t - d] : 0;
        __syncthreads();
        s[t] += u;
        __syncthreads();
    }
    int exc = s[t] - v + base[blockIdx.x];
    if (i < Nn) {
        offs[i] = exc;
        if (i == Nn - 1) offs[Nn] = exc + v;
    }
}

__global__ void k_fill(const int* __restrict__ ei, const int* __restrict__ offs,
                       int* __restrict__ degi, int* __restrict__ col, int e) {
    int i = blockIdx.x * blockDim.x + threadIdx.x;
    if (i < e) {
        int r = ei[i];
        int c = ei[e + i];
        int pos = offs[r] + atomicSub(&degi[r], 1) - 1;
        col[pos] = c;
    }
}

// ---------------- weight conversion: W[K][N] -> Wt fp16 hi/lo [N][K] ----------
__global__ void k_wconv(const float* __restrict__ W, __half* __restrict__ H,
                        __half* __restrict__ L, int K, int N) {
    int i = blockIdx.x * blockDim.x + threadIdx.x;
    if (i < K * N) {
        int k = i / N, n = i % N;
        float w = W[i];
        __half h = __float2half_rn(w);
        __half l = __float2half_rn(w - __half2float(h));
        H[(size_t)n * K + k] = h;
        L[(size_t)n * K + k] = l;
    }
}

// ---------------- fp32 -> fp16 conversion (x once per launch) -----------------
__global__ void k_f2h(const float4* __restrict__ x, uint2* __restrict__ xh, int n4) {
    int t = blockIdx.x * blockDim.x + threadIdx.x;
    if (t < n4) {
        float4 v = x[t];
        __half2 a = __floats2half2_rn(v.x, v.y);
        __half2 b = __floats2half2_rn(v.z, v.w);
        uint2 u;
        u.x = *(unsigned*)&a;
        u.y = *(unsigned*)&b;
        xh[t] = u;
    }
}

// ---------------- aggregation: warp/node, fp16 src, serial chain (R7) ---------
__device__ __forceinline__ float4 h4_to_f4(uint2 u) {
    float2 f0 = __half22float2(*reinterpret_cast<__half2*>(&u.x));
    float2 f1 = __half22float2(*reinterpret_cast<__half2*>(&u.y));
    return make_float4(f0.x, f0.y, f1.x, f1.y);
}

__global__ void k_gather_h(const int* __restrict__ offs, const int* __restrict__ col,
                           const float* __restrict__ dinv, const uint2* __restrict__ src,
                           float4* __restrict__ dst) {
    int w    = (int)((blockIdx.x * (size_t)blockDim.x + threadIdx.x) >> 5);
    int lane = threadIdx.x & 31;
    if (w >= Nn) return;

    float di = __ldg(&dinv[w]);
    float4 acc = h4_to_f4(__ldg(&src[(size_t)w * 32 + lane]));
    acc.x *= di; acc.y *= di; acc.z *= di; acc.w *= di;

    int beg = __ldg(&offs[w]), end = __ldg(&offs[w + 1]);
    int c = (beg < end) ? __ldg(&col[beg]) : 0;
    for (int j = beg; j < end; j++) {
        int cn = (j + 1 < end) ? __ldg(&col[j + 1]) : 0;
        float wc = __ldg(&dinv[c]);
        float4 v = h4_to_f4(__ldg(&src[(size_t)c * 32 + lane]));
        acc.x = fmaf(wc, v.x, acc.x);
        acc.y = fmaf(wc, v.y, acc.y);
        acc.z = fmaf(wc, v.z, acc.z);
        acc.w = fmaf(wc, v.w, acc.w);
        c = cn;
    }
    acc.x *= di; acc.y *= di; acc.z *= di; acc.w *= di;
    dst[(size_t)w * 32 + lane] = acc;
}

// ---------------- fp16 2-MMA split tensor-core GEMM ---------------------------
// A staged fp16 (single buffer); W split fp16 hi + fp16 lo; fp32 accumulate.
__device__ __forceinline__ void mma16816h(float* c, const unsigned* a, unsigned b0, unsigned b1) {
    asm volatile(
        "mma.sync.aligned.m16n8k16.row.col.f32.f16.f16.f32 "
        "{%0,%1,%2,%3},{%4,%5,%6,%7},{%8,%9},{%0,%1,%2,%3};"
        : "+f"(c[0]), "+f"(c[1]), "+f"(c[2]), "+f"(c[3])
        : "r"(a[0]), "r"(a[1]), "r"(a[2]), "r"(a[3]), "r"(b0), "r"(b1));
}

// OUTH: write fp16 output (for activations feeding the next gather)
template<int KEL, int NTILE, int NVALID, bool RELU, bool OUTH>
__global__ void k_gemm_tc(const float* __restrict__ A, const __half* __restrict__ WtH,
                          const __half* __restrict__ WtL, const float* __restrict__ bias,
                          void* __restrict__ outv, int nrows, int ldc) {
    constexpr int KSTR  = KEL + 8;
    constexpr int NT    = NTILE / 2;   // warp n-extent
    constexpr int NFRAG = NT / 8;
    extern __shared__ __half smb[];
    __half* As  = smb;                     // 128 x KSTR
    __half* WsH = As + 128 * KSTR;         // NTILE x KSTR
    __half* WsL = WsH + NTILE * KSTR;      // NTILE x KSTR

    int tid = threadIdx.x;
    int m0 = blockIdx.x * 128;
    int n0 = blockIdx.y * NTILE;

    // stage A: fp32 -> fp16
    constexpr int C4 = KEL / 4;
#pragma unroll
    for (int it = 0; it < 128 * C4 / 256; it++) {
        int i = tid + 256 * it;
        int r = i / C4, c4 = i % C4;
        float4 v = (m0 + r < nrows) ? ((const float4*)A)[(size_t)(m0 + r) * C4 + c4]
                                    : make_float4(0.f, 0.f, 0.f, 0.f);
        __half2 p0 = __floats2half2_rn(v.x, v.y);
        __half2 p1 = __floats2half2_rn(v.z, v.w);
        int o = r * KSTR + c4 * 4;
        *(__half2*)&As[o]     = p0;
        *(__half2*)&As[o + 2] = p1;
    }
    // stage Wt slice (rows n0..n0+NTILE-1), 16B chunks
    constexpr int C8 = KEL / 8;
    {
        const uint4* GH = (const uint4*)(WtH + (size_t)n0 * KEL);
        const uint4* GL = (const uint4*)(WtL + (size_t)n0 * KEL);
#pragma unroll
        for (int it = 0; it < NTILE * C8 / 256; it++) {
            int i = tid + 256 * it;
            int r = i / C8, c = i % C8;
            *(uint4*)((char*)WsH + r * (KSTR * 2) + c * 16) = GH[r * C8 + c];
            *(uint4*)((char*)WsL + r * (KSTR * 2) + c * 16) = GL[r * C8 + c];
        }
    }
    __syncthreads();

    int lane = tid & 31, wid = tid >> 5;
    int wm = (wid & 3) * 32;
    int wn = (wid >> 2) * NT;
    int g = lane >> 2, t = lane & 3;

    float acc[2][NFRAG][4];
#pragma unroll
    for (int mt = 0; mt < 2; mt++)
#pragma unroll
        for (int nt = 0; nt < NFRAG; nt++)
#pragma unroll
            for (int q = 0; q < 4; q++) acc[mt][nt][q] = 0.f;

#pragma unroll
    for (int ks = 0; ks < KEL / 16; ks++) {
        int k0 = ks * 16;
        unsigned aF[2][4];
#pragma unroll
        for (int mt = 0; mt < 2; mt++) {
            int r = wm + mt * 16;
            aF[mt][0] = *(const unsigned*)&As[(r + g) * KSTR + k0 + 2 * t];
            aF[mt][1] = *(const unsigned*)&As[(r + g + 8) * KSTR + k0 + 2 * t];
            aF[mt][2] = *(const unsigned*)&As[(r + g) * KSTR + k0 + 8 + 2 * t];
            aF[mt][3] = *(const unsigned*)&As[(r + g + 8) * KSTR + k0 + 8 + 2 * t];
        }
#pragma unroll
        for (int nt = 0; nt < NFRAG; nt++) {
            int nn = wn + nt * 8 + g;
            unsigned bH0 = *(const unsigned*)&WsH[nn * KSTR + k0 + 2 * t];
            unsigned bH1 = *(const unsigned*)&WsH[nn * KSTR + k0 + 8 + 2 * t];
            unsigned bL0 = *(const unsigned*)&WsL[nn * KSTR + k0 + 2 * t];
            unsigned bL1 = *(const unsigned*)&WsL[nn * KSTR + k0 + 8 + 2 * t];
#pragma unroll
            for (int mt = 0; mt < 2; mt++) {
                mma16816h(acc[mt][nt], aF[mt], bH0, bH1);
                mma16816h(acc[mt][nt], aF[mt], bL0, bL1);
            }
        }
    }

    // epilogue
#pragma unroll
    for (int nt = 0; nt < NFRAG; nt++) {
        int cg = n0 + wn + nt * 8 + 2 * t;
        bool cok = cg < NVALID;        // NVALID even, cg even -> covers cg+1
        float bv0 = cok ? bias[cg] : 0.f;
        float bv1 = cok ? bias[cg + 1] : 0.f;
#pragma unroll
        for (int mt = 0; mt < 2; mt++) {
            int r0 = m0 + wm + mt * 16 + g;
            float v0 = acc[mt][nt][0] + bv0, v1 = acc[mt][nt][1] + bv1;
            float v2 = acc[mt][nt][2] + bv0, v3 = acc[mt][nt][3] + bv1;
            if (RELU) {
                v0 = fmaxf(v0, 0.f); v1 = fmaxf(v1, 0.f);
                v2 = fmaxf(v2, 0.f); v3 = fmaxf(v3, 0.f);
            }
            if (OUTH) {
                __half* oh = (__half*)outv;
                if (cok && r0 < nrows)
                    *(__half2*)&oh[(size_t)r0 * ldc + cg] = __floats2half2_rn(v0, v1);
                if (cok && r0 + 8 < nrows)
                    *(__half2*)&oh[(size_t)(r0 + 8) * ldc + cg] = __floats2half2_rn(v2, v3);
            } else {
                float* of = (float*)outv;
                if (cok && r0 < nrows) {
                    of[(size_t)r0 * ldc + cg]     = v0;
                    of[(size_t)r0 * ldc + cg + 1] = v1;
                }
                if (cok && r0 + 8 < nrows) {
                    of[(size_t)(r0 + 8) * ldc + cg]     = v2;
                    of[(size_t)(r0 + 8) * ldc + cg + 1] = v3;
                }
            }
        }
    }
}

#define SMEM_TC  (3 * 128 * 136 * 2)               // 104448 (KEL=128, NTILE=128)
#define SMEM_M2  ((128 + 2 * 64) * 264 * 2)        // 135168 (KEL=256, NTILE=64)

extern "C" void kernel_launch(void* const* d_in, const int* in_sizes, int n_in,
                              void* d_out, int out_size) {
    const float* x   = (const float*)d_in[0];
    const int*   ei  = (const int*)  d_in[1];
    const float* W0  = (const float*)d_in[2];
    const float* b0  = (const float*)d_in[3];
    const float* W1  = (const float*)d_in[4];
    const float* b1  = (const float*)d_in[5];
    const float* W2  = (const float*)d_in[6];
    const float* b2  = (const float*)d_in[7];
    const float* Wm1 = (const float*)d_in[8];
    const float* bm1 = (const float*)d_in[9];
    const float* Wm2 = (const float*)d_in[10];
    const float* bm2 = (const float*)d_in[11];
    float* out = (float*)d_out;

    const int n = Nn, e = Ee;

    int *degi, *offs, *col, *part, *base;
    float *dinv, *bufA, *bufB, *hid;
    __half *xh, *actH, *wtH, *wtL;
    cudaGetSymbolAddress((void**)&degi, g_degi);
    cudaGetSymbolAddress((void**)&offs, g_offs);
    cudaGetSymbolAddress((void**)&col,  g_col);
    cudaGetSymbolAddress((void**)&part, g_part);
    cudaGetSymbolAddress((void**)&base, g_base);
    cudaGetSymbolAddress((void**)&dinv, g_dinv);
    cudaGetSymbolAddress((void**)&bufA, g_bufA);
    cudaGetSymbolAddress((void**)&bufB, g_bufB);
    cudaGetSymbolAddress((void**)&hid,  g_hid);
    cudaGetSymbolAddress((void**)&xh,   g_xh);
    cudaGetSymbolAddress((void**)&actH, g_actH);
    cudaGetSymbolAddress((void**)&wtH,  g_wtH);
    cudaGetSymbolAddress((void**)&wtL,  g_wtL);

    cudaFuncSetAttribute(k_gemm_tc<128, 128, 128, true, true>,
                         cudaFuncAttributeMaxDynamicSharedMemorySize, SMEM_TC);
    cudaFuncSetAttribute(k_gemm_tc<128, 128, 128, true, false>,
                         cudaFuncAttributeMaxDynamicSharedMemorySize, SMEM_TC);
    cudaFuncSetAttribute(k_gemm_tc<128, 128, 256, true, false>,
                         cudaFuncAttributeMaxDynamicSharedMemorySize, SMEM_TC);
    cudaFuncSetAttribute(k_gemm_tc<256, 64, 40, false, false>,
                         cudaFuncAttributeMaxDynamicSharedMemorySize, SMEM_M2);

    const int TB = 256;
    dim3 gN((n + TB - 1) / TB);
    dim3 gE((e + TB - 1) / TB);
    dim3 gNW(((size_t)n * 32 + TB - 1) / TB);
    dim3 gF2H(((size_t)n * 32 + TB - 1) / TB);
    dim3 gTC((n + 127) / 128, 1);
    dim3 gTC2((n + 127) / 128, 2);

    // ---- CSR build + normalization ----
    k_zero <<<gN, TB>>>(degi, n);
    k_count<<<gE, TB>>>(ei, degi, e);
    k_dinv <<<gN, TB>>>(degi, dinv, n);
    k_scanA<<<NB, 1024>>>(degi, part);
    k_scanB<<<1, 128>>>(part, base);
    k_scanC<<<NB, 1024>>>(degi, base, offs);
    k_fill <<<gE, TB>>>(ei, offs, degi, col, e);

    // ---- weight conversion (transposed fp16 hi/lo; Wm2 zero-padded to 64) ----
    k_bzero<<<(16384 + 255) / 256, 256>>>(wtH + WTM2, wtL + WTM2, 16384);
    k_wconv<<<(128 * 128 + 255) / 256, 256>>>(W0,  wtH + WT0,  wtL + WT0,  128, 128);
    k_wconv<<<(128 * 128 + 255) / 256, 256>>>(W1,  wtH + WT1,  wtL + WT1,  128, 128);
    k_wconv<<<(128 * 128 + 255) / 256, 256>>>(W2,  wtH + WT2,  wtL + WT2,  128, 128);
    k_wconv<<<(128 * 256 + 255) / 256, 256>>>(Wm1, wtH + WTM1, wtL + WTM1, 128, 256);
    k_wconv<<<(256 * 40 + 255) / 256, 256>>>(Wm2, wtH + WTM2, wtL + WTM2, 256, 40);

    // ---- x -> fp16 ----
    k_f2h<<<gF2H, TB>>>((const float4*)x, (uint2*)xh, n * 32);

    // ---- layer 0: gather fp16 x, GEMM -> fp16 h1 ----
    k_gather_h<<<gNW, TB>>>(offs, col, dinv, (const uint2*)xh, (float4*)bufA);
    k_gemm_tc<128, 128, 128, true, true><<<gTC, TB, SMEM_TC>>>(
        bufA, wtH + WT0, wtL + WT0, b0, actH, n, 128);

    // ---- layer 1: gather fp16 h1, GEMM -> fp16 h2 ----
    k_gather_h<<<gNW, TB>>>(offs, col, dinv, (const uint2*)actH, (float4*)bufA);
    k_gemm_tc<128, 128, 128, true, true><<<gTC, TB, SMEM_TC>>>(
        bufA, wtH + WT1, wtL + WT1, b1, actH, n, 128);

    // ---- layer 2: gather fp16 h2, GEMM -> fp32 h3 ----
    k_gather_h<<<gNW, TB>>>(offs, col, dinv, (const uint2*)actH, (float4*)bufA);
    k_gemm_tc<128, 128, 128, true, false><<<gTC, TB, SMEM_TC>>>(
        bufA, wtH + WT2, wtL + WT2, b2, bufB, n, 128);

    // ---- MLP ----
    k_gemm_tc<128, 128, 256, true, false><<<gTC2, TB, SMEM_TC>>>(
        bufB, wtH + WTM1, wtL + WTM1, bm1, hid, n, 256);
    k_gemm_tc<256, 64, 40, false, false><<<gTC, TB, SMEM_M2>>>(
        hid, wtH + WTM2, wtL + WTM2, bm2, out, n, 40);
}

// round 11
// speedup vs baseline: 1.2765x; 1.0995x over previous
#include <cuda_runtime.h>
#include <cuda_fp16.h>

#define Nn 100000
#define Ee 1600000
#define Dd 128
#define Hh 256
#define Ll 40
#define NB 98   // ceil(Nn / 1024)

// ---------------- scratch ------------------------------------------------------
__device__ int   g_degi[Nn];
__device__ int   g_offs[Nn + 1];
__device__ int   g_col[Ee];
__device__ int   g_part[NB];
__device__ int   g_base[NB];
__device__ float g_dinv[Nn];
__device__ float g_bufB[(size_t)Nn * Dd];     // h3 (fp32)
__device__ float g_hid[(size_t)Nn * Hh];      // MLP hidden
__device__ __half g_xh[(size_t)Nn * Dd];      // prescaled fp16 features (layer src)
__device__ __half g_aggH[(size_t)Nn * Dd];    // fp16 gather output
// transposed fp16 hi/lo weights [N][K]:
//   W0,W1,W2: 128x128 ; Wm1: 256x128 ; Wm2: 64(pad from 40)x256
#define WT0 0
#define WT1 16384
#define WT2 32768
#define WTM1 49152
#define WTM2 81920
__device__ __half g_wtH[98304];
__device__ __half g_wtL[98304];

// ---------------- CSR build ----------------------------------------------------
__global__ void k_zero(int* __restrict__ a, int n) {
    int i = blockIdx.x * blockDim.x + threadIdx.x;
    if (i < n) a[i] = 0;
}

__global__ void k_bzero(__half* __restrict__ a, __half* __restrict__ b, int n) {
    int i = blockIdx.x * blockDim.x + threadIdx.x;
    if (i < n) { a[i] = __float2half(0.f); b[i] = __float2half(0.f); }
}

__global__ void k_count(const int* __restrict__ ei, int* __restrict__ degi, int e) {
    int i = blockIdx.x * blockDim.x + threadIdx.x;
    if (i < e) atomicAdd(&degi[ei[i]], 1);
}

__global__ void k_dinv(const int* __restrict__ degi, float* __restrict__ dinv, int n) {
    int i = blockIdx.x * blockDim.x + threadIdx.x;
    if (i < n) dinv[i] = rsqrtf((float)degi[i] + 1.0f);
}

__global__ void k_scanA(const int* __restrict__ degi, int* __restrict__ part) {
    __shared__ int s[1024];
    int i = blockIdx.x * 1024 + threadIdx.x;
    s[threadIdx.x] = (i < Nn) ? degi[i] : 0;
    __syncthreads();
    for (int d = 512; d > 0; d >>= 1) {
        if (threadIdx.x < d) s[threadIdx.x] += s[threadIdx.x + d];
        __syncthreads();
    }
    if (threadIdx.x == 0) part[blockIdx.x] = s[0];
}

__global__ void k_scanB(const int* __restrict__ part, int* __restrict__ base) {
    __shared__ int s[128];
    int t = threadIdx.x;
    int v = (t < NB) ? part[t] : 0;
    s[t] = v;
    __syncthreads();
    for (int d = 1; d < 128; d <<= 1) {
        int u = (t >= d) ? s[t - d] : 0;
        __syncthreads();
        s[t] += u;
        __syncthreads();
    }
    if (t < NB) base[t] = s[t] - v;
}

__global__ void k_scanC(const int* __restrict__ degi, const int* __restrict__ base,
                        int* __restrict__ offs) {
    __shared__ int s[1024];
    int t = threadIdx.x;
    int i = blockIdx.x * 1024 + t;
    int v = (i < Nn) ? degi[i] : 0;
    s[t] = v;
    __syncthreads();
    for (int d = 1; d < 1024; d <<= 1) {
        int u = (t >= d) ? s[t - d] : 0;
        __syncthreads();
        s[t] += u;
        __syncthreads();
    }
    int exc = s[t] - v + base[blockIdx.x];
    if (i < Nn) {
        offs[i] = exc;
        if (i == Nn - 1) offs[Nn] = exc + v;
    }
}

__global__ void k_fill(const int* __restrict__ ei, const int* __restrict__ offs,
                       int* __restrict__ degi, int* __restrict__ col, int e) {
    int i = blockIdx.x * blockDim.x + threadIdx.x;
    if (i < e) {
        int r = ei[i];
        int c = ei[e + i];
        int pos = offs[r] + atomicSub(&degi[r], 1) - 1;
        col[pos] = c;
    }
}

// ---------------- weight conversion: W[K][N] -> Wt fp16 hi/lo [N][K] ----------
__global__ void k_wconv(const float* __restrict__ W, __half* __restrict__ H,
                        __half* __restrict__ L, int K, int N) {
    int i = blockIdx.x * blockDim.x + threadIdx.x;
    if (i < K * N) {
        int k = i / N, n = i % N;
        float w = W[i];
        __half h = __float2half_rn(w);
        __half l = __float2half_rn(w - __half2float(h));
        H[(size_t)n * K + k] = h;
        L[(size_t)n * K + k] = l;
    }
}

// ---------------- fp32 -> prescaled fp16: xh = fp16(dinv[row] * x) ------------
__global__ void k_f2h(const float4* __restrict__ x, const float* __restrict__ dinv,
                      uint2* __restrict__ xh, int n4) {
    int t = blockIdx.x * blockDim.x + threadIdx.x;
    if (t < n4) {
        float d = __ldg(&dinv[t >> 5]);
        float4 v = x[t];
        __half2 a = __floats2half2_rn(v.x * d, v.y * d);
        __half2 b = __floats2half2_rn(v.z * d, v.w * d);
        uint2 u;
        u.x = *(unsigned*)&a;
        u.y = *(unsigned*)&b;
        xh[t] = u;
    }
}

// ---------------- aggregation: warp/node, prescaled fp16, pure sum ------------
// src[c] = fp16(dinv[c]*h[c]);  dst[r] = fp16( dinv[r] * (src[r] + sum src[c]) )
__device__ __forceinline__ float4 h4_to_f4(uint2 u) {
    float2 f0 = __half22float2(*reinterpret_cast<__half2*>(&u.x));
    float2 f1 = __half22float2(*reinterpret_cast<__half2*>(&u.y));
    return make_float4(f0.x, f0.y, f1.x, f1.y);
}

__global__ void k_gather_h(const int* __restrict__ offs, const int* __restrict__ col,
                           const float* __restrict__ dinv, const uint2* __restrict__ src,
                           uint2* __restrict__ dst) {
    int w    = (int)((blockIdx.x * (size_t)blockDim.x + threadIdx.x) >> 5);
    int lane = threadIdx.x & 31;
    if (w >= Nn) return;

    float4 acc = h4_to_f4(__ldg(&src[(size_t)w * 32 + lane]));   // self term

    int beg = __ldg(&offs[w]), end = __ldg(&offs[w + 1]);
    int c = (beg < end) ? __ldg(&col[beg]) : 0;
    for (int j = beg; j < end; j++) {
        int cn = (j + 1 < end) ? __ldg(&col[j + 1]) : 0;   // prefetch next index
        float4 v = h4_to_f4(__ldg(&src[(size_t)c * 32 + lane]));
        acc.x += v.x; acc.y += v.y; acc.z += v.z; acc.w += v.w;
        c = cn;
    }
    float di = __ldg(&dinv[w]);
    __half2 p0 = __floats2half2_rn(acc.x * di, acc.y * di);
    __half2 p1 = __floats2half2_rn(acc.z * di, acc.w * di);
    uint2 u;
    u.x = *(unsigned*)&p0;
    u.y = *(unsigned*)&p1;
    dst[(size_t)w * 32 + lane] = u;
}

// ---------------- fp16 2-MMA split tensor-core GEMM ---------------------------
__device__ __forceinline__ void mma16816h(float* c, const unsigned* a, unsigned b0, unsigned b1) {
    asm volatile(
        "mma.sync.aligned.m16n8k16.row.col.f32.f16.f16.f32 "
        "{%0,%1,%2,%3},{%4,%5,%6,%7},{%8,%9},{%0,%1,%2,%3};"
        : "+f"(c[0]), "+f"(c[1]), "+f"(c[2]), "+f"(c[3])
        : "r"(a[0]), "r"(a[1]), "r"(a[2]), "r"(a[3]), "r"(b0), "r"(b1));
}

// INH: A operand is fp16 in gmem (raw copy); else fp32 (convert while staging).
// OUTH: write prescaled fp16 activations: fp16(dinv[row] * relu(...)).
template<int KEL, int NTILE, int NVALID, bool RELU, bool OUTH, bool INH>
__global__ void k_gemm_tc(const void* __restrict__ Av, const __half* __restrict__ WtH,
                          const __half* __restrict__ WtL, const float* __restrict__ bias,
                          const float* __restrict__ dinv, void* __restrict__ outv,
                          int nrows, int ldc) {
    constexpr int KSTR  = KEL + 8;
    constexpr int NT    = NTILE / 2;   // warp n-extent
    constexpr int NFRAG = NT / 8;
    extern __shared__ __half smb[];
    __half* As  = smb;                     // 128 x KSTR
    __half* WsH = As + 128 * KSTR;         // NTILE x KSTR
    __half* WsL = WsH + NTILE * KSTR;      // NTILE x KSTR

    int tid = threadIdx.x;
    int m0 = blockIdx.x * 128;
    int n0 = blockIdx.y * NTILE;

    constexpr int C8 = KEL / 8;   // uint4 chunks per row (8 halfs each)
    if (INH) {
        // stage A: raw fp16 copy, 16B chunks
        const uint4* GA = (const uint4*)Av;
#pragma unroll
        for (int it = 0; it < 128 * C8 / 256; it++) {
            int i = tid + 256 * it;
            int r = i / C8, c = i % C8;
            uint4 v = (m0 + r < nrows) ? __ldg(&GA[(size_t)(m0 + r) * C8 + c])
                                       : make_uint4(0u, 0u, 0u, 0u);
            *(uint4*)&As[r * KSTR + c * 8] = v;
        }
    } else {
        // stage A: fp32 -> fp16 convert
        constexpr int C4 = KEL / 4;
        const float4* GA = (const float4*)Av;
#pragma unroll
        for (int it = 0; it < 128 * C4 / 256; it++) {
            int i = tid + 256 * it;
            int r = i / C4, c4 = i % C4;
            float4 v = (m0 + r < nrows) ? GA[(size_t)(m0 + r) * C4 + c4]
                                        : make_float4(0.f, 0.f, 0.f, 0.f);
            __half2 p0 = __floats2half2_rn(v.x, v.y);
            __half2 p1 = __floats2half2_rn(v.z, v.w);
            int o = r * KSTR + c4 * 4;
            *(__half2*)&As[o]     = p0;
            *(__half2*)&As[o + 2] = p1;
        }
    }
    // stage Wt slice (rows n0..n0+NTILE-1), 16B chunks
    {
        const uint4* GH = (const uint4*)(WtH + (size_t)n0 * KEL);
        const uint4* GL = (const uint4*)(WtL + (size_t)n0 * KEL);
#pragma unroll
        for (int it = 0; it < NTILE * C8 / 256; it++) {
            int i = tid + 256 * it;
            int r = i / C8, c = i % C8;
            *(uint4*)((char*)WsH + r * (KSTR * 2) + c * 16) = GH[r * C8 + c];
            *(uint4*)((char*)WsL + r * (KSTR * 2) + c * 16) = GL[r * C8 + c];
        }
    }
    __syncthreads();

    int lane = tid & 31, wid = tid >> 5;
    int wm = (wid & 3) * 32;
    int wn = (wid >> 2) * NT;
    int g = lane >> 2, t = lane & 3;

    float acc[2][NFRAG][4];
#pragma unroll
    for (int mt = 0; mt < 2; mt++)
#pragma unroll
        for (int nt = 0; nt < NFRAG; nt++)
#pragma unroll
            for (int q = 0; q < 4; q++) acc[mt][nt][q] = 0.f;

#pragma unroll
    for (int ks = 0; ks < KEL / 16; ks++) {
        int k0 = ks * 16;
        unsigned aF[2][4];
#pragma unroll
        for (int mt = 0; mt < 2; mt++) {
            int r = wm + mt * 16;
            aF[mt][0] = *(const unsigned*)&As[(r + g) * KSTR + k0 + 2 * t];
            aF[mt][1] = *(const unsigned*)&As[(r + g + 8) * KSTR + k0 + 2 * t];
            aF[mt][2] = *(const unsigned*)&As[(r + g) * KSTR + k0 + 8 + 2 * t];
            aF[mt][3] = *(const unsigned*)&As[(r + g + 8) * KSTR + k0 + 8 + 2 * t];
        }
#pragma unroll
        for (int nt = 0; nt < NFRAG; nt++) {
            int nn = wn + nt * 8 + g;
            unsigned bH0 = *(const unsigned*)&WsH[nn * KSTR + k0 + 2 * t];
            unsigned bH1 = *(const unsigned*)&WsH[nn * KSTR + k0 + 8 + 2 * t];
            unsigned bL0 = *(const unsigned*)&WsL[nn * KSTR + k0 + 2 * t];
            unsigned bL1 = *(const unsigned*)&WsL[nn * KSTR + k0 + 8 + 2 * t];
#pragma unroll
            for (int mt = 0; mt < 2; mt++) {
                mma16816h(acc[mt][nt], aF[mt], bH0, bH1);
                mma16816h(acc[mt][nt], aF[mt], bL0, bL1);
            }
        }
    }

    // epilogue
#pragma unroll
    for (int nt = 0; nt < NFRAG; nt++) {
        int cg = n0 + wn + nt * 8 + 2 * t;
        bool cok = cg < NVALID;        // NVALID even, cg even -> covers cg+1
        float bv0 = cok ? bias[cg] : 0.f;
        float bv1 = cok ? bias[cg + 1] : 0.f;
#pragma unroll
        for (int mt = 0; mt < 2; mt++) {
            int r0 = m0 + wm + mt * 16 + g;
            float v0 = acc[mt][nt][0] + bv0, v1 = acc[mt][nt][1] + bv1;
            float v2 = acc[mt][nt][2] + bv0, v3 = acc[mt][nt][3] + bv1;
            if (RELU) {
                v0 = fmaxf(v0, 0.f); v1 = fmaxf(v1, 0.f);
                v2 = fmaxf(v2, 0.f); v3 = fmaxf(v3, 0.f);
            }
            if (OUTH) {
                // prescale by dinv[row], store fp16
                float d0 = (r0 < nrows) ? __ldg(&dinv[r0]) : 0.f;
                float d1 = (r0 + 8 < nrows) ? __ldg(&dinv[r0 + 8]) : 0.f;
                __half* oh = (__half*)outv;
                if (cok && r0 < nrows)
                    *(__half2*)&oh[(size_t)r0 * ldc + cg] = __floats2half2_rn(v0 * d0, v1 * d0);
                if (cok && r0 + 8 < nrows)
                    *(__half2*)&oh[(size_t)(r0 + 8) * ldc + cg] = __floats2half2_rn(v2 * d1, v3 * d1);
            } else {
                float* of = (float*)outv;
                if (cok && r0 < nrows) {
                    of[(size_t)r0 * ldc + cg]     = v0;
                    of[(size_t)r0 * ldc + cg + 1] = v1;
                }
                if (cok && r0 + 8 < nrows) {
                    of[(size_t)(r0 + 8) * ldc + cg]     = v2;
                    of[(size_t)(r0 + 8) * ldc + cg + 1] = v3;
                }
            }
        }
    }
}

#define SMEM_TC  (3 * 128 * 136 * 2)               // 104448 (KEL=128, NTILE=128)
#define SMEM_M2  ((128 + 2 * 64) * 264 * 2)        // 135168 (KEL=256, NTILE=64)

extern "C" void kernel_launch(void* const* d_in, const int* in_sizes, int n_in,
                              void* d_out, int out_size) {
    const float* x   = (const float*)d_in[0];
    const int*   ei  = (const int*)  d_in[1];
    const float* W0  = (const float*)d_in[2];
    const float* b0  = (const float*)d_in[3];
    const float* W1  = (const float*)d_in[4];
    const float* b1  = (const float*)d_in[5];
    const float* W2  = (const float*)d_in[6];
    const float* b2  = (const float*)d_in[7];
    const float* Wm1 = (const float*)d_in[8];
    const float* bm1 = (const float*)d_in[9];
    const float* Wm2 = (const float*)d_in[10];
    const float* bm2 = (const float*)d_in[11];
    float* out = (float*)d_out;

    const int n = Nn, e = Ee;

    int *degi, *offs, *col, *part, *base;
    float *dinv, *bufB, *hid;
    __half *xh, *aggH, *wtH, *wtL;
    cudaGetSymbolAddress((void**)&degi, g_degi);
    cudaGetSymbolAddress((void**)&offs, g_offs);
    cudaGetSymbolAddress((void**)&col,  g_col);
    cudaGetSymbolAddress((void**)&part, g_part);
    cudaGetSymbolAddress((void**)&base, g_base);
    cudaGetSymbolAddress((void**)&dinv, g_dinv);
    cudaGetSymbolAddress((void**)&bufB, g_bufB);
    cudaGetSymbolAddress((void**)&hid,  g_hid);
    cudaGetSymbolAddress((void**)&xh,   g_xh);
    cudaGetSymbolAddress((void**)&aggH, g_aggH);
    cudaGetSymbolAddress((void**)&wtH,  g_wtH);
    cudaGetSymbolAddress((void**)&wtL,  g_wtL);

    cudaFuncSetAttribute(k_gemm_tc<128, 128, 128, true, true, true>,
                         cudaFuncAttributeMaxDynamicSharedMemorySize, SMEM_TC);
    cudaFuncSetAttribute(k_gemm_tc<128, 128, 128, true, false, true>,
                         cudaFuncAttributeMaxDynamicSharedMemorySize, SMEM_TC);
    cudaFuncSetAttribute(k_gemm_tc<128, 128, 256, true, false, false>,
                         cudaFuncAttributeMaxDynamicSharedMemorySize, SMEM_TC);
    cudaFuncSetAttribute(k_gemm_tc<256, 64, 40, false, false, false>,
                         cudaFuncAttributeMaxDynamicSharedMemorySize, SMEM_M2);

    const int TB = 256;
    dim3 gN((n + TB - 1) / TB);
    dim3 gE((e + TB - 1) / TB);
    dim3 gNW(((size_t)n * 32 + TB - 1) / TB);
    dim3 gF2H(((size_t)n * 32 + TB - 1) / TB);
    dim3 gTC((n + 127) / 128, 1);
    dim3 gTC2((n + 127) / 128, 2);

    // ---- CSR build + normalization ----
    k_zero <<<gN, TB>>>(degi, n);
    k_count<<<gE, TB>>>(ei, degi, e);
    k_dinv <<<gN, TB>>>(degi, dinv, n);
    k_scanA<<<NB, 1024>>>(degi, part);
    k_scanB<<<1, 128>>>(part, base);
    k_scanC<<<NB, 1024>>>(degi, base, offs);
    k_fill <<<gE, TB>>>(ei, offs, degi, col, e);

    // ---- weight conversion (transposed fp16 hi/lo; Wm2 zero-padded to 64) ----
    k_bzero<<<(16384 + 255) / 256, 256>>>(wtH + WTM2, wtL + WTM2, 16384);
    k_wconv<<<(128 * 128 + 255) / 256, 256>>>(W0,  wtH + WT0,  wtL + WT0,  128, 128);
    k_wconv<<<(128 * 128 + 255) / 256, 256>>>(W1,  wtH + WT1,  wtL + WT1,  128, 128);
    k_wconv<<<(128 * 128 + 255) / 256, 256>>>(W2,  wtH + WT2,  wtL + WT2,  128, 128);
    k_wconv<<<(128 * 256 + 255) / 256, 256>>>(Wm1, wtH + WTM1, wtL + WTM1, 128, 256);
    k_wconv<<<(256 * 40 + 255) / 256, 256>>>(Wm2, wtH + WTM2, wtL + WTM2, 256, 40);

    // ---- x -> prescaled fp16 ----
    k_f2h<<<gF2H, TB>>>((const float4*)x, dinv, (uint2*)xh, n * 32);

    // ---- layer 0: gather -> fp16 agg, GEMM -> prescaled fp16 h1 ----
    k_gather_h<<<gNW, TB>>>(offs, col, dinv, (const uint2*)xh, (uint2*)aggH);
    k_gemm_tc<128, 128, 128, true, true, true><<<gTC, TB, SMEM_TC>>>(
        aggH, wtH + WT0, wtL + WT0, b0, dinv, xh, n, 128);

    // ---- layer 1: gather fp16 h1, GEMM -> prescaled fp16 h2 ----
    k_gather_h<<<gNW, TB>>>(offs, col, dinv, (const uint2*)xh, (uint2*)aggH);
    k_gemm_tc<128, 128, 128, true, true, true><<<gTC, TB, SMEM_TC>>>(
        aggH, wtH + WT1, wtL + WT1, b1, dinv, xh, n, 128);

    // ---- layer 2: gather fp16 h2, GEMM -> fp32 h3 ----
    k_gather_h<<<gNW, TB>>>(offs, col, dinv, (const uint2*)xh, (uint2*)aggH);
    k_gemm_tc<128, 128, 128, true, false, true><<<gTC, TB, SMEM_TC>>>(
        aggH, wtH + WT2, wtL + WT2, b2, dinv, bufB, n, 128);

    // ---- MLP ----
    k_gemm_tc<128, 128, 256, true, false, false><<<gTC2, TB, SMEM_TC>>>(
        bufB, wtH + WTM1, wtL + WTM1, bm1, dinv, hid, n, 256);
    k_gemm_tc<256, 64, 40, false, false, false><<<gTC, TB, SMEM_M2>>>(
        hid, wtH + WTM2, wtL + WTM2, bm2, dinv, out, n, 40);
}

// round 13
// speedup vs baseline: 1.4984x; 1.1739x over previous
#include <cuda_runtime.h>
#include <cuda_fp16.h>

#define Nn 100000
#define Ee 1600000
#define Dd 128
#define Hh 256
#define Ll 40
#define NB 98   // ceil(Nn / 1024)

// ---------------- scratch ------------------------------------------------------
__device__ int   g_degi[Nn];
__device__ int   g_offs[Nn + 1];
__device__ int   g_col[Ee];
__device__ int   g_part[NB];
__device__ float g_dinv[Nn];
__device__ __half g_xh[(size_t)Nn * Dd];      // prescaled fp16 features / h3
__device__ __half g_aggH[(size_t)Nn * Dd];    // fp16 gather output
__device__ __half g_hidH[(size_t)Nn * Hh];    // fp16 MLP hidden
// transposed fp16 hi/lo weights [N][K], packed:
//   W0,W1,W2: 128x128 ; Wm1: 256x128 ; Wm2: 64(pad from 40)x256
#define WT0 0
#define WT1 16384
#define WT2 32768
#define WTM1 49152
#define WTM2 81920
#define WTOT 98304
__device__ __half g_wtH[WTOT];
__device__ __half g_wtL[WTOT];

// ---------------- CSR build ----------------------------------------------------
__global__ void k_zero(int* __restrict__ a, int n) {
    int i = blockIdx.x * blockDim.x + threadIdx.x;
    if (i < n) a[i] = 0;
}

__global__ void k_count(const int* __restrict__ ei, int* __restrict__ degi, int e) {
    int i = blockIdx.x * blockDim.x + threadIdx.x;
    if (i < e) atomicAdd(&degi[ei[i]], 1);
}

// block partial sums + dinv (fused)
__global__ void k_scanA(const int* __restrict__ degi, int* __restrict__ part,
                        float* __restrict__ dinv) {
    __shared__ int s[1024];
    int i = blockIdx.x * 1024 + threadIdx.x;
    int v = (i < Nn) ? degi[i] : 0;
    if (i < Nn) dinv[i] = rsqrtf((float)v + 1.0f);
    s[threadIdx.x] = v;
    __syncthreads();
    for (int d = 512; d > 0; d >>= 1) {
        if (threadIdx.x < d) s[threadIdx.x] += s[threadIdx.x + d];
        __syncthreads();
    }
    if (threadIdx.x == 0) part[blockIdx.x] = s[0];
}

// per-block exclusive scan; base computed in-block from partials (fused scanB)
__global__ void k_scanC(const int* __restrict__ degi, const int* __restrict__ part,
                        int* __restrict__ offs) {
    __shared__ int sp[128];
    __shared__ int s[1024];
    int t = threadIdx.x;
    if (t < 128) sp[t] = (t < NB) ? part[t] : 0;
    __syncthreads();
    for (int d = 1; d < 128; d <<= 1) {
        int u = 0;
        if (t < 128 && t >= d) u = sp[t - d];
        __syncthreads();
        if (t < 128) sp[t] += u;
        __syncthreads();
    }
    int base = (blockIdx.x == 0) ? 0 : sp[blockIdx.x - 1];
    int i = blockIdx.x * 1024 + t;
    int v = (i < Nn) ? degi[i] : 0;
    s[t] = v;
    __syncthreads();
    for (int d = 1; d < 1024; d <<= 1) {
        int u = (t >= d) ? s[t - d] : 0;
        __syncthreads();
        s[t] += u;
        __syncthreads();
    }
    int exc = s[t] - v + base;
    if (i < Nn) {
        offs[i] = exc;
        if (i == Nn - 1) offs[Nn] = exc + v;
    }
}

__global__ void k_fill(const int* __restrict__ ei, const int* __restrict__ offs,
                       int* __restrict__ degi, int* __restrict__ col, int e) {
    int i = blockIdx.x * blockDim.x + threadIdx.x;
    if (i < e) {
        int r = ei[i];
        int c = ei[e + i];
        int pos = offs[r] + atomicSub(&degi[r], 1) - 1;
        col[pos] = c;
    }
}

// ---------------- fused weight conversion: all 5 weights -> fp16 hi/lo --------
__global__ void k_wconv_all(const float* __restrict__ W0, const float* __restrict__ W1,
                            const float* __restrict__ W2, const float* __restrict__ Wm1,
                            const float* __restrict__ Wm2,
                            __half* __restrict__ H, __half* __restrict__ L) {
    int i = blockIdx.x * blockDim.x + threadIdx.x;
    if (i >= WTOT) return;
    float w;
    if (i < WTM1) {                       // W0/W1/W2: dest [n][k], K=128, N=128
        const float* W = (i < WT1) ? W0 : (i < WT2) ? W1 : W2;
        int j = i & 16383;
        int n = j >> 7, k = j & 127;
        w = W[k * 128 + n];
    } else if (i < WTM2) {                // Wm1: dest [n][k], n<256, K=128
        int j = i - WTM1;
        int n = j >> 7, k = j & 127;
        w = Wm1[k * 256 + n];
    } else {                              // Wm2: dest [n][k], n<64 (pad 40), K=256
        int j = i - WTM2;
        int n = j >> 8, k = j & 255;
        w = (n < Ll) ? Wm2[k * Ll + n] : 0.f;
    }
    __half h = __float2half_rn(w);
    __half l = __float2half_rn(w - __half2float(h));
    H[i] = h;
    L[i] = l;
}

// ---------------- fp32 -> prescaled fp16: xh = fp16(dinv[row] * x) ------------
__global__ void k_f2h(const float4* __restrict__ x, const float* __restrict__ dinv,
                      uint2* __restrict__ xh, int n4) {
    int t = blockIdx.x * blockDim.x + threadIdx.x;
    if (t < n4) {
        float d = __ldg(&dinv[t >> 5]);
        float4 v = x[t];
        __half2 a = __floats2half2_rn(v.x * d, v.y * d);
        __half2 b = __floats2half2_rn(v.z * d, v.w * d);
        uint2 u;
        u.x = *(unsigned*)&a;
        u.y = *(unsigned*)&b;
        xh[t] = u;
    }
}

// ---------------- aggregation: warp/node, prescaled fp16, pure sum ------------
__device__ __forceinline__ float4 h4_to_f4(uint2 u) {
    float2 f0 = __half22float2(*reinterpret_cast<__half2*>(&u.x));
    float2 f1 = __half22float2(*reinterpret_cast<__half2*>(&u.y));
    return make_float4(f0.x, f0.y, f1.x, f1.y);
}

__global__ void k_gather_h(const int* __restrict__ offs, const int* __restrict__ col,
                           const float* __restrict__ dinv, const uint2* __restrict__ src,
                           uint2* __restrict__ dst) {
    int w    = (int)((blockIdx.x * (size_t)blockDim.x + threadIdx.x) >> 5);
    int lane = threadIdx.x & 31;
    if (w >= Nn) return;

    float4 acc = h4_to_f4(__ldg(&src[(size_t)w * 32 + lane]));   // self term

    int beg = __ldg(&offs[w]), end = __ldg(&offs[w + 1]);
    int c = (beg < end) ? __ldg(&col[beg]) : 0;
    for (int j = beg; j < end; j++) {
        int cn = (j + 1 < end) ? __ldg(&col[j + 1]) : 0;   // prefetch next index
        float4 v = h4_to_f4(__ldg(&src[(size_t)c * 32 + lane]));
        acc.x += v.x; acc.y += v.y; acc.z += v.z; acc.w += v.w;
        c = cn;
    }
    float di = __ldg(&dinv[w]);
    __half2 p0 = __floats2half2_rn(acc.x * di, acc.y * di);
    __half2 p1 = __floats2half2_rn(acc.z * di, acc.w * di);
    uint2 u;
    u.x = *(unsigned*)&p0;
    u.y = *(unsigned*)&p1;
    dst[(size_t)w * 32 + lane] = u;
}

// ---------------- fp16 2-MMA split tensor-core GEMM ---------------------------
__device__ __forceinline__ void mma16816h(float* c, const unsigned* a, unsigned b0, unsigned b1) {
    asm volatile(
        "mma.sync.aligned.m16n8k16.row.col.f32.f16.f16.f32 "
        "{%0,%1,%2,%3},{%4,%5,%6,%7},{%8,%9},{%0,%1,%2,%3};"
        : "+f"(c[0]), "+f"(c[1]), "+f"(c[2]), "+f"(c[3])
        : "r"(a[0]), "r"(a[1]), "r"(a[2]), "r"(a[3]), "r"(b0), "r"(b1));
}

// A always fp16 in gmem (raw 16B copy staging).
// OUTH: write fp16; PRESCALE: multiply rows by dinv before store (requires OUTH).
template<int KEL, int NTILE, int NVALID, bool RELU, bool OUTH, bool PRESCALE>
__global__ void k_gemm_tc(const __half* __restrict__ Ah, const __half* __restrict__ WtH,
                          const __half* __restrict__ WtL, const float* __restrict__ bias,
                          const float* __restrict__ dinv, void* __restrict__ outv,
                          int nrows, int ldc) {
    constexpr int KSTR  = KEL + 8;
    constexpr int NT    = NTILE / 2;   // warp n-extent
    constexpr int NFRAG = NT / 8;
    extern __shared__ __half smb[];
    __half* As  = smb;                     // 128 x KSTR
    __half* WsH = As + 128 * KSTR;         // NTILE x KSTR
    __half* WsL = WsH + NTILE * KSTR;      // NTILE x KSTR

    int tid = threadIdx.x;
    int m0 = blockIdx.x * 128;
    int n0 = blockIdx.y * NTILE;

    constexpr int C8 = KEL / 8;   // uint4 chunks per row (8 halfs each)
    // stage A: raw fp16 copy, 16B chunks
    {
        const uint4* GA = (const uint4*)Ah;
#pragma unroll
        for (int it = 0; it < 128 * C8 / 256; it++) {
            int i = tid + 256 * it;
            int r = i / C8, c = i % C8;
            uint4 v = (m0 + r < nrows) ? __ldg(&GA[(size_t)(m0 + r) * C8 + c])
                                       : make_uint4(0u, 0u, 0u, 0u);
            *(uint4*)&As[r * KSTR + c * 8] = v;
        }
    }
    // stage Wt slice (rows n0..n0+NTILE-1), 16B chunks
    {
        const uint4* GH = (const uint4*)(WtH + (size_t)n0 * KEL);
        const uint4* GL = (const uint4*)(WtL + (size_t)n0 * KEL);
#pragma unroll
        for (int it = 0; it < NTILE * C8 / 256; it++) {
            int i = tid + 256 * it;
            int r = i / C8, c = i % C8;
            *(uint4*)((char*)WsH + r * (KSTR * 2) + c * 16) = GH[r * C8 + c];
            *(uint4*)((char*)WsL + r * (KSTR * 2) + c * 16) = GL[r * C8 + c];
        }
    }
    __syncthreads();

    int lane = tid & 31, wid = tid >> 5;
    int wm = (wid & 3) * 32;
    int wn = (wid >> 2) * NT;
    int g = lane >> 2, t = lane & 3;

    float acc[2][NFRAG][4];
#pragma unroll
    for (int mt = 0; mt < 2; mt++)
#pragma unroll
        for (int nt = 0; nt < NFRAG; nt++)
#pragma unroll
            for (int q = 0; q < 4; q++) acc[mt][nt][q] = 0.f;

#pragma unroll
    for (int ks = 0; ks < KEL / 16; ks++) {
        int k0 = ks * 16;
        unsigned aF[2][4];
#pragma unroll
        for (int mt = 0; mt < 2; mt++) {
            int r = wm + mt * 16;
            aF[mt][0] = *(const unsigned*)&As[(r + g) * KSTR + k0 + 2 * t];
            aF[mt][1] = *(const unsigned*)&As[(r + g + 8) * KSTR + k0 + 2 * t];
            aF[mt][2] = *(const unsigned*)&As[(r + g) * KSTR + k0 + 8 + 2 * t];
            aF[mt][3] = *(const unsigned*)&As[(r + g + 8) * KSTR + k0 + 8 + 2 * t];
        }
#pragma unroll
        for (int nt = 0; nt < NFRAG; nt++) {
            int nn = wn + nt * 8 + g;
            unsigned bH0 = *(const unsigned*)&WsH[nn * KSTR + k0 + 2 * t];
            unsigned bH1 = *(const unsigned*)&WsH[nn * KSTR + k0 + 8 + 2 * t];
            unsigned bL0 = *(const unsigned*)&WsL[nn * KSTR + k0 + 2 * t];
            unsigned bL1 = *(const unsigned*)&WsL[nn * KSTR + k0 + 8 + 2 * t];
#pragma unroll
            for (int mt = 0; mt < 2; mt++) {
                mma16816h(acc[mt][nt], aF[mt], bH0, bH1);
                mma16816h(acc[mt][nt], aF[mt], bL0, bL1);
            }
        }
    }

    // epilogue
#pragma unroll
    for (int nt = 0; nt < NFRAG; nt++) {
        int cg = n0 + wn + nt * 8 + 2 * t;
        bool cok = cg < NVALID;        // NVALID even, cg even -> covers cg+1
        float bv0 = cok ? bias[cg] : 0.f;
        float bv1 = cok ? bias[cg + 1] : 0.f;
#pragma unroll
        for (int mt = 0; mt < 2; mt++) {
            int r0 = m0 + wm + mt * 16 + g;
            float v0 = acc[mt][nt][0] + bv0, v1 = acc[mt][nt][1] + bv1;
            float v2 = acc[mt][nt][2] + bv0, v3 = acc[mt][nt][3] + bv1;
            if (RELU) {
                v0 = fmaxf(v0, 0.f); v1 = fmaxf(v1, 0.f);
                v2 = fmaxf(v2, 0.f); v3 = fmaxf(v3, 0.f);
            }
            if (OUTH) {
                float d0 = 1.f, d1 = 1.f;
                if (PRESCALE) {
                    d0 = (r0 < nrows) ? __ldg(&dinv[r0]) : 0.f;
                    d1 = (r0 + 8 < nrows) ? __ldg(&dinv[r0 + 8]) : 0.f;
                }
                __half* oh = (__half*)outv;
                if (cok && r0 < nrows)
                    *(__half2*)&oh[(size_t)r0 * ldc + cg] = __floats2half2_rn(v0 * d0, v1 * d0);
                if (cok && r0 + 8 < nrows)
                    *(__half2*)&oh[(size_t)(r0 + 8) * ldc + cg] = __floats2half2_rn(v2 * d1, v3 * d1);
            } else {
                float* of = (float*)outv;
                if (cok && r0 < nrows) {
                    of[(size_t)r0 * ldc + cg]     = v0;
                    of[(size_t)r0 * ldc + cg + 1] = v1;
                }
                if (cok && r0 + 8 < nrows) {
                    of[(size_t)(r0 + 8) * ldc + cg]     = v2;
                    of[(size_t)(r0 + 8) * ldc + cg + 1] = v3;
                }
            }
        }
    }
}

#define SMEM_TC  (3 * 128 * 136 * 2)               // 104448 (KEL=128, NTILE=128)
#define SMEM_M2  ((128 + 2 * 64) * 264 * 2)        // 135168 (KEL=256, NTILE=64)

extern "C" void kernel_launch(void* const* d_in, const int* in_sizes, int n_in,
                              void* d_out, int out_size) {
    const float* x   = (const float*)d_in[0];
    const int*   ei  = (const int*)  d_in[1];
    const float* W0  = (const float*)d_in[2];
    const float* b0  = (const float*)d_in[3];
    const float* W1  = (const float*)d_in[4];
    const float* b1  = (const float*)d_in[5];
    const float* W2  = (const float*)d_in[6];
    const float* b2  = (const float*)d_in[7];
    const float* Wm1 = (const float*)d_in[8];
    const float* bm1 = (const float*)d_in[9];
    const float* Wm2 = (const float*)d_in[10];
    const float* bm2 = (const float*)d_in[11];
    float* out = (float*)d_out;

    const int n = Nn, e = Ee;

    int *degi, *offs, *col, *part;
    float *dinv;
    __half *xh, *aggH, *hidH, *wtH, *wtL;
    cudaGetSymbolAddress((void**)&degi, g_degi);
    cudaGetSymbolAddress((void**)&offs, g_offs);
    cudaGetSymbolAddress((void**)&col,  g_col);
    cudaGetSymbolAddress((void**)&part, g_part);
    cudaGetSymbolAddress((void**)&dinv, g_dinv);
    cudaGetSymbolAddress((void**)&xh,   g_xh);
    cudaGetSymbolAddress((void**)&aggH, g_aggH);
    cudaGetSymbolAddress((void**)&hidH, g_hidH);
    cudaGetSymbolAddress((void**)&wtH,  g_wtH);
    cudaGetSymbolAddress((void**)&wtL,  g_wtL);

    cudaFuncSetAttribute(k_gemm_tc<128, 128, 128, true, true, true>,
                         cudaFuncAttributeMaxDynamicSharedMemorySize, SMEM_TC);
    cudaFuncSetAttribute(k_gemm_tc<128, 128, 128, true, true, false>,
                         cudaFuncAttributeMaxDynamicSharedMemorySize, SMEM_TC);
    cudaFuncSetAttribute(k_gemm_tc<128, 128, 256, true, true, false>,
                         cudaFuncAttributeMaxDynamicSharedMemorySize, SMEM_TC);
    cudaFuncSetAttribute(k_gemm_tc<256, 64, 40, false, false, false>,
                         cudaFuncAttributeMaxDynamicSharedMemorySize, SMEM_M2);

    const int TB = 256;
    dim3 gN((n + TB - 1) / TB);
    dim3 gE((e + TB - 1) / TB);
    dim3 gNW(((size_t)n * 32 + TB - 1) / TB);
    dim3 gF2H(((size_t)n * 32 + TB - 1) / TB);
    dim3 gTC((n + 127) / 128, 1);
    dim3 gTC2((n + 127) / 128, 2);

    // ---- CSR build + normalization (5 launches) ----
    k_zero <<<gN, TB>>>(degi, n);
    k_count<<<gE, TB>>>(ei, degi, e);
    k_scanA<<<NB, 1024>>>(degi, part, dinv);
    k_scanC<<<NB, 1024>>>(degi, part, offs);
    k_fill <<<gE, TB>>>(ei, offs, degi, col, e);

    // ---- fused weight conversion (1 launch) ----
    k_wconv_all<<<(WTOT + 255) / 256, 256>>>(W0, W1, W2, Wm1, Wm2, wtH, wtL);

    // ---- x -> prescaled fp16 ----
    k_f2h<<<gF2H, TB>>>((const float4*)x, dinv, (uint2*)xh, n * 32);

    // ---- layer 0: gather -> fp16 agg, GEMM -> prescaled fp16 h1 (in xh) ----
    k_gather_h<<<gNW, TB>>>(offs, col, dinv, (const uint2*)xh, (uint2*)aggH);
    k_gemm_tc<128, 128, 128, true, true, true><<<gTC, TB, SMEM_TC>>>(
        aggH, wtH + WT0, wtL + WT0, b0, dinv, xh, n, 128);

    // ---- layer 1 ----
    k_gather_h<<<gNW, TB>>>(offs, col, dinv, (const uint2*)xh, (uint2*)aggH);
    k_gemm_tc<128, 128, 128, true, true, true><<<gTC, TB, SMEM_TC>>>(
        aggH, wtH + WT1, wtL + WT1, b1, dinv, xh, n, 128);

    // ---- layer 2: gather, GEMM -> plain fp16 h3 (in xh) ----
    k_gather_h<<<gNW, TB>>>(offs, col, dinv, (const uint2*)xh, (uint2*)aggH);
    k_gemm_tc<128, 128, 128, true, true, false><<<gTC, TB, SMEM_TC>>>(
        aggH, wtH + WT2, wtL + WT2, b2, dinv, xh, n, 128);

    // ---- MLP: h3(fp16) -> hid(fp16) -> out(fp32) ----
    k_gemm_tc<128, 128, 256, true, true, false><<<gTC2, TB, SMEM_TC>>>(
        xh, wtH + WTM1, wtL + WTM1, bm1, dinv, hidH, n, 256);
    k_gemm_tc<256, 64, 40, false, false, false><<<gTC, TB, SMEM_M2>>>(
        hidH, wtH + WTM2, wtL + WTM2, bm2, dinv, out, n, 40);
}